// round 1
// baseline (speedup 1.0000x reference)
#include <cuda_runtime.h>

#define NB 2
#define NN 192
#define NF 5
#define NPAIR ((NN*(NN-1))/2)   // 18336 pairs j<k
#define THREADS 256

__device__ __forceinline__ float ex2f(float x) {
    float y;
    asm("ex2.approx.ftz.f32 %0, %1;" : "=f"(y) : "f"(x));
    return y;
}

__device__ __forceinline__ float sqrt_approx(float x) {
    float y;
    asm("sqrt.approx.f32 %0, %1;" : "=f"(y) : "f"(x));
    return y;
}

__global__ __launch_bounds__(THREADS)
void fa_kernel(const float* __restrict__ d, const float* __restrict__ cd,
               const float* __restrict__ fp, const float* __restrict__ coeff,
               float* __restrict__ out)
{
    const int b = blockIdx.x / NN;
    const int i = blockIdx.x % NN;
    const int tid = threadIdx.x;

    __shared__ float sD2[NN];   // d[i,k]^2
    __shared__ float sRh[NN];   // sqrt(0.5)/d[i,k], 0 at k==i
    __shared__ float sWq[NN];   // sqrt(2)*cd0[i,k], 0 at k==i
    __shared__ float sFp[NF], sC2[NF];
    __shared__ float sRed[8*NF];
    __shared__ float sS[8], sSS[8];
    __shared__ float sCdii;

    if (tid < NF) {
        sFp[tid] = fp[tid];
        // temp = exp(-100*coeff*diff^2) = ex2( (-100*coeff*log2e) * diff^2 )
        sC2[tid] = -144.26950408889634f * coeff[tid];
    }

    const float* __restrict__ drow  = d  + ((size_t)b*NN + i)*NN;
    const float* __restrict__ cdrow = cd + ((size_t)b*NN + i)*NN;

    // Phase 1: per-k row precompute + partial sums S, SS
    float pS = 0.f, pSS = 0.f;
    for (int k = tid; k < NN; k += THREADS) {
        float dv = drow[k];
        float cv = cdrow[k];
        float c0 = (cv == 1.0f) ? 0.0f : cv;
        pS  += c0;
        pSS += c0*c0;
        bool isI = (k == i);
        sD2[k] = dv*dv;
        sRh[k] = isI ? 0.0f : 0.70710678118654752f / dv;
        sWq[k] = isI ? 0.0f : 1.41421356237309515f * c0;
        if (isI) sCdii = c0;
    }
    #pragma unroll
    for (int o = 16; o; o >>= 1) {
        pS  += __shfl_down_sync(0xFFFFFFFFu, pS,  o);
        pSS += __shfl_down_sync(0xFFFFFFFFu, pSS, o);
    }
    if ((tid & 31) == 0) { sS[tid>>5] = pS; sSS[tid>>5] = pSS; }
    __syncthreads();

    const float fp0 = sFp[0], fp1 = sFp[1], fp2 = sFp[2], fp3 = sFp[3], fp4 = sFp[4];
    const float c20 = sC2[0], c21 = sC2[1], c22 = sC2[2], c23 = sC2[3], c24 = sC2[4];
    const float* __restrict__ dmat = d + (size_t)b*NN*NN;

    float acc0 = 0.f, acc1 = 0.f, acc2 = 0.f, acc3 = 0.f, acc4 = 0.f;

    // Phase 2: strictly-lower-triangle pairs p = k*(k-1)/2 + j, 0 <= j < k < NN.
    // j==i / k==i rows contribute 0 here (sRh/sWq masked), handled analytically.
    for (int p = tid; p < NPAIR; p += THREADS) {
        // invert triangular index (sqrt.approx + exact integer fixup)
        float s = sqrt_approx((float)(8*p + 1));
        int k = (int)((1.0f + s) * 0.5f);
        int rs = (k*(k-1)) >> 1;
        if (rs > p)                 { k--; rs = (k*(k-1)) >> 1; }
        else if (((k*(k+1)) >> 1) <= p) { k++; rs = (k*(k-1)) >> 1; }
        int j = p - rs;

        float djk = __ldg(&dmat[k*NN + j]);           // d[b,k,j] == d[b,j,k]
        float num = (sD2[j] + sD2[k]) - djk*djk;
        float a   = num * sRh[j] * sRh[k];            // = num / (2 d_ij d_ik)
        float w   = sWq[j] * sWq[k];                  // = 2 cd0_j cd0_k

        float df, arg;
        df = a - fp0; arg = (c20*df)*df; acc0 = fmaf(ex2f(arg), w, acc0);
        df = a - fp1; arg = (c21*df)*df; acc1 = fmaf(ex2f(arg), w, acc1);
        df = a - fp2; arg = (c22*df)*df; acc2 = fmaf(ex2f(arg), w, acc2);
        df = a - fp3; arg = (c23*df)*df; acc3 = fmaf(ex2f(arg), w, acc3);
        df = a - fp4; arg = (c24*df)*df; acc4 = fmaf(ex2f(arg), w, acc4);
    }

    // Reduce 5 accumulators: warp shuffle, then cross-warp via smem
    #pragma unroll
    for (int o = 16; o; o >>= 1) {
        acc0 += __shfl_down_sync(0xFFFFFFFFu, acc0, o);
        acc1 += __shfl_down_sync(0xFFFFFFFFu, acc1, o);
        acc2 += __shfl_down_sync(0xFFFFFFFFu, acc2, o);
        acc3 += __shfl_down_sync(0xFFFFFFFFu, acc3, o);
        acc4 += __shfl_down_sync(0xFFFFFFFFu, acc4, o);
    }
    if ((tid & 31) == 0) {
        int w5 = (tid >> 5) * NF;
        sRed[w5+0] = acc0; sRed[w5+1] = acc1; sRed[w5+2] = acc2;
        sRed[w5+3] = acc3; sRed[w5+4] = acc4;
    }
    __syncthreads();

    if (tid < NF) {
        float t = 0.f;
        #pragma unroll
        for (int wi = 0; wi < 8; wi++) t += sRed[wi*NF + tid];
        float S = 0.f, SS = 0.f;
        #pragma unroll
        for (int wi = 0; wi < 8; wi++) { S += sS[wi]; SS += sSS[wi]; }
        float cii = sCdii;
        float fpv = sFp[tid], c2v = sC2[tid];
        float g0 = ex2f((c2v*fpv)*fpv);               // a = 0 terms (j==i or k==i)
        float d1 = 1.0f - fpv;
        float g1 = ex2f((c2v*d1)*d1);                 // a = 1 terms (diagonal j==k!=i)
        t += g0 * cii * (2.0f*S - cii) + g1 * (SS - cii*cii);
        out[blockIdx.x*NF + tid] = t * (1.0f / (NN * 12));
    }
}

extern "C" void kernel_launch(void* const* d_in, const int* in_sizes, int n_in,
                              void* d_out, int out_size)
{
    const float* d     = (const float*)d_in[0];   // (B,N,N)
    const float* cd    = (const float*)d_in[1];   // (B,N,N)
    const float* fp    = (const float*)d_in[2];   // (5,)
    const float* coeff = (const float*)d_in[3];   // (5,)
    float* out = (float*)d_out;                   // (B,N,5)

    fa_kernel<<<NB*NN, THREADS>>>(d, cd, fp, coeff, out);
}

// round 2
// speedup vs baseline: 1.1597x; 1.1597x over previous
#include <cuda_runtime.h>

#define NB 2
#define NN 192
#define NF 5
#define THREADS 256
#define NWARP 8

__device__ __forceinline__ float ex2f(float x) {
    float y;
    asm("ex2.approx.ftz.f32 %0, %1;" : "=f"(y) : "f"(x));
    return y;
}

__global__ __launch_bounds__(THREADS)
void fa_kernel(const float* __restrict__ d, const float* __restrict__ cd,
               const float* __restrict__ fp, const float* __restrict__ coeff,
               float* __restrict__ out)
{
    const int b    = blockIdx.x / NN;
    const int i    = blockIdx.x % NN;
    const int tid  = threadIdx.x;
    const int lane = tid & 31;
    const int w    = tid >> 5;

    __shared__ float4 sP[NN];        // (d^2, 1/(sqrt2*d), sqrt2*cd0, 0) ; masked at k==i
    __shared__ float  sFp[NF], sC2[NF];
    __shared__ float  sRed[NWARP * NF];
    __shared__ float  sS[NWARP], sSS[NWARP];
    __shared__ float  sCdii;

    if (tid < NF) {
        sFp[tid] = fp[tid];
        // exp(-100*coeff*x^2) = ex2( (-100*coeff*log2e) * x^2 )
        sC2[tid] = -144.26950408889634f * coeff[tid];
    }

    const float* __restrict__ drow  = d  + ((size_t)b * NN + i) * NN;
    const float* __restrict__ cdrow = cd + ((size_t)b * NN + i) * NN;

    // ---- Phase 1: per-k row precompute + partial sums of cd0 and cd0^2 ----
    float pS = 0.f, pSS = 0.f;
    if (tid < NN) {
        float dv = drow[tid];
        float cv = cdrow[tid];
        float c0 = (cv == 1.0f) ? 0.0f : cv;
        pS  = c0;
        pSS = c0 * c0;
        bool isI = (tid == i);
        float rh = isI ? 0.0f : 0.70710678118654752f / dv;
        float wq = isI ? 0.0f : 1.41421356237309515f * c0;
        sP[tid] = make_float4(dv * dv, rh, wq, 0.0f);
        if (isI) sCdii = c0;
    }
    #pragma unroll
    for (int o = 16; o; o >>= 1) {
        pS  += __shfl_down_sync(0xFFFFFFFFu, pS,  o);
        pSS += __shfl_down_sync(0xFFFFFFFFu, pSS, o);
    }
    if (lane == 0) { sS[w] = pS; sSS[w] = pSS; }
    __syncthreads();

    // Per-feature constants in registers: arg = c2*a^2 + m*a + q  ==  c2*(a-fp)^2
    float c2r[NF], mr[NF], qr[NF], acc[NF];
    #pragma unroll
    for (int f = 0; f < NF; f++) {
        float fpv = sFp[f], c2 = sC2[f];
        c2r[f] = c2;
        mr[f]  = -2.0f * c2 * fpv;
        qr[f]  = c2 * fpv * fpv;
        acc[f] = 0.0f;
    }

    // ---- Phase 2: strictly-lower triangle, warp w handles rows k ≡ w (mod 8) ----
    const float* __restrict__ dmat = d + (size_t)b * NN * NN;

    for (int k = w; k < NN; k += NWARP) {
        if (k == i) continue;                 // whole row masked out
        float4 Pk = sP[k];
        const float D2k = Pk.x, rk = Pk.y, wk = Pk.z;
        const float* __restrict__ rowk = dmat + k * NN;

        int j = lane;
        if (j >= k) continue;                 // lane has no work in this row
        float  dv = __ldg(rowk + j);          // prefetched current
        float4 Pj = sP[j];

        while (true) {
            float  cur = dv;
            float4 Pc  = Pj;
            int    jn  = j + 32;
            bool   more = (jn < k);
            if (more) { dv = __ldg(rowk + jn); Pj = sP[jn]; }  // prefetch next

            float num = fmaf(-cur, cur, D2k + Pc.x);   // d2j + d2k - djk^2
            float a   = (num * rk) * Pc.y;             // num / (2 d_ij d_ik)
            float a2  = a * a;
            float wgt = wk * Pc.z;                     // 2 * cd0_j * cd0_k

            #pragma unroll
            for (int f = 0; f < NF; f++) {
                float arg = fmaf(c2r[f], a2, fmaf(mr[f], a, qr[f]));
                acc[f] = fmaf(ex2f(arg), wgt, acc[f]);
            }

            if (!more) break;
            j = jn;
        }
    }

    // ---- Reduce 5 accumulators ----
    #pragma unroll
    for (int f = 0; f < NF; f++) {
        #pragma unroll
        for (int o = 16; o; o >>= 1)
            acc[f] += __shfl_down_sync(0xFFFFFFFFu, acc[f], o);
    }
    if (lane == 0) {
        #pragma unroll
        for (int f = 0; f < NF; f++) sRed[w * NF + f] = acc[f];
    }
    __syncthreads();

    if (tid < NF) {
        float t = 0.f;
        #pragma unroll
        for (int wi = 0; wi < NWARP; wi++) t += sRed[wi * NF + tid];
        float S = 0.f, SS = 0.f;
        #pragma unroll
        for (int wi = 0; wi < NWARP; wi++) { S += sS[wi]; SS += sSS[wi]; }
        float cii = sCdii;
        float fpv = sFp[tid], c2v = sC2[tid];
        float g0 = ex2f((c2v * fpv) * fpv);        // a = 0 terms (j==i or k==i)
        float d1 = 1.0f - fpv;
        float g1 = ex2f((c2v * d1) * d1);          // a = 1 terms (diagonal j==k!=i)
        t += g0 * cii * (2.0f * S - cii) + g1 * (SS - cii * cii);
        out[blockIdx.x * NF + tid] = t * (1.0f / (NN * 12));
    }
}

extern "C" void kernel_launch(void* const* d_in, const int* in_sizes, int n_in,
                              void* d_out, int out_size)
{
    const float* d     = (const float*)d_in[0];   // (B,N,N)
    const float* cd    = (const float*)d_in[1];   // (B,N,N)
    const float* fp    = (const float*)d_in[2];   // (5,)
    const float* coeff = (const float*)d_in[3];   // (5,)
    float* out = (float*)d_out;                   // (B,N,5)

    fa_kernel<<<NB * NN, THREADS>>>(d, cd, fp, coeff, out);
}